// round 1
// baseline (speedup 1.0000x reference)
#include <cuda_runtime.h>

#define BATCH 2
#define SEQ   1024
#define HS    768
#define NH    12
#define HD    64
#define WIN   64
#define HALF  32
#define MTOK  (BATCH*SEQ)   // 2048

// Scratch (device globals: no allocation allowed in kernel_launch)
__device__ float g_q[MTOK*HS];
__device__ float g_k[MTOK*HS];
__device__ float g_v[MTOK*HS];
__device__ float g_ctx[MTOK*HS];

// ---------------------------------------------------------------------------
// 128x128 tile SGEMM: C[M,N] = A[M,K] @ W[N,K]^T + bias,  K=N=768 fixed here.
// 256 threads, 8x8 microtile per thread, BK=8.
// ---------------------------------------------------------------------------
__device__ __forceinline__ void sgemm_128x128(
    const float* __restrict__ A, const float* __restrict__ W,
    const float* __restrict__ bias, float* __restrict__ C,
    int bx, int by)
{
    __shared__ float As[8][128];
    __shared__ float Bs[8][128];

    const int K = HS;
    const int tid = threadIdx.x;
    const int tx = tid & 15;      // 0..15 -> N microtile
    const int ty = tid >> 4;      // 0..15 -> M microtile
    const int lr = tid >> 1;      // load row 0..127
    const int lc = (tid & 1) * 4; // 0 or 4

    const float* Ap = A + (size_t)(by * 128 + lr) * K + lc;
    const float* Bp = W + (size_t)(bx * 128 + lr) * K + lc;

    float acc[8][8];
    #pragma unroll
    for (int i = 0; i < 8; i++)
        #pragma unroll
        for (int j = 0; j < 8; j++) acc[i][j] = 0.f;

    for (int kt = 0; kt < K; kt += 8) {
        float4 av = *(const float4*)(Ap + kt);
        float4 bv = *(const float4*)(Bp + kt);
        As[lc + 0][lr] = av.x; As[lc + 1][lr] = av.y;
        As[lc + 2][lr] = av.z; As[lc + 3][lr] = av.w;
        Bs[lc + 0][lr] = bv.x; Bs[lc + 1][lr] = bv.y;
        Bs[lc + 2][lr] = bv.z; Bs[lc + 3][lr] = bv.w;
        __syncthreads();

        #pragma unroll
        for (int k = 0; k < 8; k++) {
            float a[8], b[8];
            float4 a0 = *(const float4*)&As[k][ty * 8];
            float4 a1 = *(const float4*)&As[k][ty * 8 + 4];
            float4 b0 = *(const float4*)&Bs[k][tx * 8];
            float4 b1 = *(const float4*)&Bs[k][tx * 8 + 4];
            a[0]=a0.x; a[1]=a0.y; a[2]=a0.z; a[3]=a0.w;
            a[4]=a1.x; a[5]=a1.y; a[6]=a1.z; a[7]=a1.w;
            b[0]=b0.x; b[1]=b0.y; b[2]=b0.z; b[3]=b0.w;
            b[4]=b1.x; b[5]=b1.y; b[6]=b1.z; b[7]=b1.w;
            #pragma unroll
            for (int i = 0; i < 8; i++)
                #pragma unroll
                for (int j = 0; j < 8; j++)
                    acc[i][j] += a[i] * b[j];
        }
        __syncthreads();
    }

    const int row0 = by * 128 + ty * 8;
    const int col0 = bx * 128 + tx * 8;
    float bb[8];
    #pragma unroll
    for (int j = 0; j < 8; j++) bb[j] = bias[col0 + j];

    #pragma unroll
    for (int i = 0; i < 8; i++) {
        float4 o0, o1;
        o0.x = acc[i][0] + bb[0]; o0.y = acc[i][1] + bb[1];
        o0.z = acc[i][2] + bb[2]; o0.w = acc[i][3] + bb[3];
        o1.x = acc[i][4] + bb[4]; o1.y = acc[i][5] + bb[5];
        o1.z = acc[i][6] + bb[6]; o1.w = acc[i][7] + bb[7];
        float* Cp = C + (size_t)(row0 + i) * HS + col0;
        *(float4*)(Cp)     = o0;
        *(float4*)(Cp + 4) = o1;
    }
}

__global__ __launch_bounds__(256) void qkv_kernel(
    const float* __restrict__ X,
    const float* __restrict__ Wq, const float* __restrict__ bq,
    const float* __restrict__ Wk, const float* __restrict__ bk,
    const float* __restrict__ Wv, const float* __restrict__ bv)
{
    const float* W; const float* b; float* C;
    if (blockIdx.z == 0)      { W = Wq; b = bq; C = g_q; }
    else if (blockIdx.z == 1) { W = Wk; b = bk; C = g_k; }
    else                      { W = Wv; b = bv; C = g_v; }
    sgemm_128x128(X, W, b, C, blockIdx.x, blockIdx.y);
}

__global__ __launch_bounds__(256) void out_kernel(
    const float* __restrict__ Wo, const float* __restrict__ bo,
    float* __restrict__ out)
{
    sgemm_128x128(g_ctx, Wo, bo, out, blockIdx.x, blockIdx.y);
}

// ---------------------------------------------------------------------------
// Sliding-window attention. Block = 8 queries of one (batch, head).
// One warp per query; exact zero-padding semantics (OOB score = 0, v = 0).
// ---------------------------------------------------------------------------
__global__ __launch_bounds__(256) void attn_kernel()
{
    __shared__ float Ks[71][65];   // keys s0-32 .. s0+38, padded stride 65
    __shared__ float Vs[71][65];
    __shared__ float Qs[8][64];
    __shared__ float Ps[8][64];

    const int s0 = blockIdx.x * 8;
    const int h  = blockIdx.y;
    const int b  = blockIdx.z;
    const int tid = threadIdx.x;
    const int base = (b * SEQ) * HS + h * HD;

    // Stage K/V window (zero-fill out-of-range rows)
    for (int i = tid; i < 71 * 64; i += 256) {
        int r = i >> 6, d = i & 63;
        int j = s0 - HALF + r;
        float kv = 0.f, vv = 0.f;
        if (j >= 0 && j < SEQ) {
            int off = base + j * HS + d;
            kv = g_k[off];
            vv = g_v[off];
        }
        Ks[r][d] = kv;
        Vs[r][d] = vv;
    }
    for (int i = tid; i < 8 * 64; i += 256) {
        int r = i >> 6, d = i & 63;
        Qs[r][d] = g_q[base + (s0 + r) * HS + d];
    }
    __syncthreads();

    const int wq   = tid >> 5;   // query within block (warp id)
    const int lane = tid & 31;

    // Scores: lane owns window slots {lane, lane+32}
    float sc0 = 0.f, sc1 = 0.f;
    #pragma unroll
    for (int d = 0; d < 64; d++) {
        float qd = Qs[wq][d];
        sc0 += qd * Ks[wq + lane][d];
        sc1 += qd * Ks[wq + lane + 32][d];
    }
    sc0 *= 0.125f;   // 1/sqrt(64)
    sc1 *= 0.125f;

    // Warp softmax over 64 slots
    float m = fmaxf(sc0, sc1);
    #pragma unroll
    for (int o = 16; o; o >>= 1) m = fmaxf(m, __shfl_xor_sync(0xFFFFFFFFu, m, o));
    float e0 = __expf(sc0 - m);
    float e1 = __expf(sc1 - m);
    float sum = e0 + e1;
    #pragma unroll
    for (int o = 16; o; o >>= 1) sum += __shfl_xor_sync(0xFFFFFFFFu, sum, o);
    float inv = 1.f / sum;
    Ps[wq][lane]      = e0 * inv;
    Ps[wq][lane + 32] = e1 * inv;
    __syncwarp();

    // Context: lane owns dims {lane, lane+32}
    float c0 = 0.f, c1 = 0.f;
    #pragma unroll
    for (int w = 0; w < 64; w++) {
        float p = Ps[wq][w];
        c0 += p * Vs[wq + w][lane];
        c1 += p * Vs[wq + w][lane + 32];
    }
    int orow = base + (s0 + wq) * HS;
    g_ctx[orow + lane]      = c0;
    g_ctx[orow + lane + 32] = c1;
}

// ---------------------------------------------------------------------------
extern "C" void kernel_launch(void* const* d_in, const int* in_sizes, int n_in,
                              void* d_out, int out_size)
{
    const float* X  = (const float*)d_in[0];
    const float* Wq = (const float*)d_in[1];
    const float* bq = (const float*)d_in[2];
    const float* Wk = (const float*)d_in[3];
    const float* bk = (const float*)d_in[4];
    const float* Wv = (const float*)d_in[5];
    const float* bv = (const float*)d_in[6];
    const float* Wo = (const float*)d_in[7];
    const float* bo = (const float*)d_in[8];
    float* out = (float*)d_out;

    dim3 gemm_grid(HS / 128, MTOK / 128, 3);     // (6, 16, 3)
    qkv_kernel<<<gemm_grid, 256>>>(X, Wq, bq, Wk, bk, Wv, bv);

    dim3 attn_grid(SEQ / 8, NH, BATCH);          // (128, 12, 2)
    attn_kernel<<<attn_grid, 256>>>();

    dim3 out_grid(HS / 128, MTOK / 128, 1);      // (6, 16)
    out_kernel<<<out_grid, 256>>>(Wo, bo, out);
}